// round 8
// baseline (speedup 1.0000x reference)
#include <cuda_runtime.h>

// LSTM: B=256, T=2048, F=64, U=10. Gates i,f,g,o; g=softsign; h=o*softsign(c);
// head = sigmoid(h@dw+db).
//
// SINGLE fused kernel, 86 blocks x 256 threads (block = 3 batches):
//   warps {0,1,2,4,5,6} : producers — GEMM xz = x@W+bias, chunk-major
//                         (64 t/chunk), unit-major layout, 0.5 prescale i,f,o.
//   warp 3              : exits immediately (keeps SMSP3 clear).
//   warp 7              : consumer scan — EXCLUSIVE SMSP3.
// Scan inner loop: j-pairwise fma.rn.f32x2 (20 FFMA2/step), h-pairs packed
// once and shared by all 4 gates; shfl lane indices hoisted.

#define BB 256
#define TT 2048
#define FF 64
#define UU 10
#define GG 40
#define CH 64
#define NCHUNK (TT / CH)

__device__ float g_xz[(size_t)BB * TT * GG];   // 83.9 MB scratch

typedef unsigned long long u64;

__device__ __forceinline__ u64 pack2(float x, float y) {
    u64 d; asm("mov.b64 %0, {%1, %2};" : "=l"(d) : "f"(x), "f"(y)); return d;
}
__device__ __forceinline__ void unpack2(u64 a, float& x, float& y) {
    asm("mov.b64 {%0, %1}, %2;" : "=f"(x), "=f"(y) : "l"(a));
}
__device__ __forceinline__ u64 ffma2(u64 a, u64 b, u64 c) {
    u64 d; asm("fma.rn.f32x2 %0, %1, %2, %3;" : "=l"(d) : "l"(a), "l"(b), "l"(c));
    return d;
}
__device__ __forceinline__ float tanh_ap(float x) {
    float r; asm("tanh.approx.f32 %0, %1;" : "=f"(r) : "f"(x)); return r;
}
__device__ __forceinline__ float rcp_ap(float x) {
    float r; asm("rcp.approx.f32 %0, %1;" : "=f"(r) : "f"(x)); return r;
}
__device__ __forceinline__ void bar_producers() {
    asm volatile("bar.sync 1, 192;" ::: "memory");
}

// ---------------------------------------------------------------------------
// scan inner: 8 steps. 5 h-pairs shared across 4 gates; 5-deep FFMA2 chains.
// ---------------------------------------------------------------------------
__device__ __forceinline__ void scan_group8(
        const float4*& pf, float4 buf[8],
        const u64 Rip[5], const u64 Rfp[5], const u64 Rgp[5], const u64 Rop[5],
        float& h, float& c, const int li[UU], bool doLoad) {
#pragma unroll
    for (int p = 0; p < 8; ++p) {
        const float4 z4 = buf[p];
        if (doLoad) buf[p] = pf[(size_t)p * UU];

        float hs[UU];
#pragma unroll
        for (int j = 0; j < UU; ++j)
            hs[j] = __shfl_sync(0xffffffffu, h, li[j]);

        u64 hp[5];
#pragma unroll
        for (int j = 0; j < 5; ++j) hp[j] = pack2(hs[2 * j], hs[2 * j + 1]);

        // per-gate 5-deep FFMA2 chain; accumulator seeded with (z, 0)
        u64 zi2 = ffma2(hp[0], Rip[0], pack2(z4.x, 0.f));
        u64 zf2 = ffma2(hp[0], Rfp[0], pack2(z4.y, 0.f));
        u64 zg2 = ffma2(hp[0], Rgp[0], pack2(z4.z, 0.f));
        u64 zo2 = ffma2(hp[0], Rop[0], pack2(z4.w, 0.f));
#pragma unroll
        for (int j = 1; j < 5; ++j) {
            zi2 = ffma2(hp[j], Rip[j], zi2);
            zf2 = ffma2(hp[j], Rfp[j], zf2);
            zg2 = ffma2(hp[j], Rgp[j], zg2);
            zo2 = ffma2(hp[j], Rop[j], zo2);
        }
        float a, b;
        unpack2(zi2, a, b); const float zi = a + b;
        unpack2(zf2, a, b); const float zf = a + b;
        unpack2(zg2, a, b); const float zg = a + b;
        unpack2(zo2, a, b); const float zo = a + b;

        // sigmoid(2z) = 0.5*tanh(z)+0.5  (z holds 0.5*logit for i,f,o)
        const float ig = fmaf(0.5f, tanh_ap(zi), 0.5f);
        const float fg = fmaf(0.5f, tanh_ap(zf), 0.5f);
        const float og = fmaf(0.5f, tanh_ap(zo), 0.5f);
        const float gg = zg * rcp_ap(1.0f + fabsf(zg));     // softsign
        c = fmaf(fg, c, ig * gg);
        const float r = rcp_ap(1.0f + fabsf(c));
        h = (og * c) * r;                                    // o*softsign(c)
    }
    pf += 8 * UU;
}

// ---------------------------------------------------------------------------
__global__ void __launch_bounds__(256, 1) fused_lstm_kernel(
        const float* __restrict__ x,     // [256,2048,64]
        const float* __restrict__ W,     // [64,40]
        const float* __restrict__ R,     // [10,40]
        const float* __restrict__ bias,  // [40]
        const float* __restrict__ dw,    // [10]
        const float* __restrict__ db,    // [1]
        float* __restrict__ out) {       // [256]
    __shared__ float Wt[GG][FF + 4];
    __shared__ float bs[GG];
    __shared__ volatile unsigned int counter;

    const int tid = threadIdx.x;
    const int wid = tid >> 5;
    const int lane = tid & 31;

    if (tid == 0) counter = 0u;
    for (int i = tid; i < FF * GG; i += 256) {
        int k = i / GG, col = i - k * GG;
        Wt[col][k] = W[i];
    }
    if (tid < GG) bs[tid] = bias[tid];
    __syncthreads();

    if (wid == 3) return;   // keep SMSP3 exclusive for the scan warp (wid 7)

    if (wid != 7) {
        // ---- producers: wids {0,1,2,4,5,6} -> rows 0..191 -------------------
        const int pw = (wid < 3) ? wid : wid - 1;   // 0..5
        const int row = pw * 32 + lane;
        const int bi = row >> 6;
        const int tloc = row & 63;
        int gb = blockIdx.x * 3 + bi;
        if (gb > BB - 1) gb = BB - 1;   // clamp: dup writes carry same values
        const size_t rowbase = (size_t)gb * TT + tloc;

        for (int k = 0; k < NCHUNK; ++k) {
            const size_t t = rowbase + (size_t)k * CH;
            const float4* xr = reinterpret_cast<const float4*>(x + t * FF);
            float4 xv[16];
#pragma unroll
            for (int i = 0; i < 16; ++i) xv[i] = xr[i];

            float acc[GG];
#pragma unroll
            for (int col = 0; col < GG; ++col) acc[col] = 0.f;

#pragma unroll
            for (int k4 = 0; k4 < 16; ++k4) {
                const float4 xq = xv[k4];
#pragma unroll
                for (int col = 0; col < GG; ++col) {
                    const float4 w =
                        *reinterpret_cast<const float4*>(&Wt[col][k4 * 4]);
                    float a = acc[col];
                    a = fmaf(xq.x, w.x, a);
                    a = fmaf(xq.y, w.y, a);
                    a = fmaf(xq.z, w.z, a);
                    acc[col] = fmaf(xq.w, w.w, a);
                }
            }

            float4* op = reinterpret_cast<float4*>(&g_xz[t * GG]);
#pragma unroll
            for (int u = 0; u < UU; ++u) {
                float4 v;
                v.x = 0.5f * (acc[u] + bs[u]);               // i
                v.y = 0.5f * (acc[10 + u] + bs[10 + u]);     // f
                v.z =        (acc[20 + u] + bs[20 + u]);     // g
                v.w = 0.5f * (acc[30 + u] + bs[30 + u]);     // o
                op[u] = v;
            }

            __threadfence_block();
            bar_producers();
            if (tid == 0) counter = (unsigned)(k + 1);
        }
    } else {
        // ---- consumer: warp 7, exclusive SMSP3 ------------------------------
        const int grp = lane / UU;          // 0..3 (3 = dummy lanes 30,31)
        const int u = lane - grp * UU;
        const int batch = blockIdx.x * 3 + grp;
        const bool valid = (grp < 3) && (batch < BB);
        const int bc = valid ? batch : (BB - 1);
        const int base = grp * UU;

        int li[UU];                          // hoisted shfl lane indices
#pragma unroll
        for (int j = 0; j < UU; ++j) li[j] = base + j;

        // j-pairwise packed weights (0.5 prescale on i,f,o columns)
        u64 Rip[5], Rfp[5], Rgp[5], Rop[5];
#pragma unroll
        for (int j = 0; j < 5; ++j) {
            const int j0 = 2 * j, j1 = 2 * j + 1;
            Rip[j] = pack2(0.5f * R[j0 * GG + u],          0.5f * R[j1 * GG + u]);
            Rfp[j] = pack2(0.5f * R[j0 * GG + UU + u],     0.5f * R[j1 * GG + UU + u]);
            Rgp[j] = pack2(       R[j0 * GG + 2 * UU + u],        R[j1 * GG + 2 * UU + u]);
            Rop[j] = pack2(0.5f * R[j0 * GG + 3 * UU + u], 0.5f * R[j1 * GG + 3 * UU + u]);
        }
        float dwr[UU];
#pragma unroll
        for (int j = 0; j < UU; ++j) dwr[j] = dw[j];

        const float4* xzp =
            reinterpret_cast<const float4*>(g_xz) + (size_t)bc * TT * UU + u;

        while (counter < 1u) __nanosleep(64);
        __threadfence_block();
        __syncwarp();

        float4 buf[8];
#pragma unroll
        for (int p = 0; p < 8; ++p) buf[p] = xzp[(size_t)p * UU];
        const float4* pf = xzp + 8 * UU;

        float h = 0.f, c = 0.f;

        for (int k = 0; k < NCHUNK; ++k) {
            if (k < NCHUNK - 1) {
                while (counter < (unsigned)(k + 2)) __nanosleep(64);
                __threadfence_block();
                __syncwarp();
                for (int g8 = 0; g8 < 8; ++g8)
                    scan_group8(pf, buf, Rip, Rfp, Rgp, Rop, h, c, li, true);
            } else {
                for (int g8 = 0; g8 < 7; ++g8)
                    scan_group8(pf, buf, Rip, Rfp, Rgp, Rop, h, c, li, true);
                scan_group8(pf, buf, Rip, Rfp, Rgp, Rop, h, c, li, false);
            }
        }

        float logit = db[0];
#pragma unroll
        for (int j = 0; j < UU; ++j)
            logit = fmaf(__shfl_sync(0xffffffffu, h, li[j]), dwr[j], logit);
        if (valid && u == 0)
            out[batch] = __fdividef(1.f, 1.f + __expf(-logit));
    }
}

// ---------------------------------------------------------------------------
extern "C" void kernel_launch(void* const* d_in, const int* in_sizes, int n_in,
                              void* d_out, int out_size) {
    const float* x    = (const float*)d_in[0];
    const float* W    = (const float*)d_in[1];
    const float* R    = (const float*)d_in[2];
    const float* bias = (const float*)d_in[3];
    const float* dw   = (const float*)d_in[4];
    const float* db   = (const float*)d_in[5];
    float* out = (float*)d_out;

    fused_lstm_kernel<<<(BB + 2) / 3, 256>>>(x, W, R, bias, dw, db, out);
}